// round 3
// baseline (speedup 1.0000x reference)
#include <cuda_runtime.h>
#include <math.h>

// Problem constants
#define B_  8
#define S_  1024
#define C_  768
#define H_  12
#define D_  64
#define BS_ (B_ * S_)           // 8192
#define BHSD (B_ * H_ * S_ * D_) // 6291456

// Scratch (allocation-free: static device globals)
__device__ float g_q[BHSD];
__device__ float g_k[BHSD];
__device__ float g_v[BHSD];
__device__ float g_y[BS_ * C_];

// ---------------------------------------------------------------------------
// SGEMM NT: C[m,n] = sum_k A[m,k] * B[n,k] (+ bias[n])
// A: [M,K] row-major, B: [N,K] row-major. 128x128 block tile, BK=8,
// 256 threads, 8x8 per-thread microtile.
// MODE 0: A = x, scatter into g_q/g_k/g_v ([B,H,S,D]) with b_qkv
// MODE 1: A = g_y, write Cout (d_out) with b_out
// ---------------------------------------------------------------------------
template <int MODE>
__global__ __launch_bounds__(256) void sgemm_nt(
    const float* __restrict__ Ain, const float* __restrict__ Bm,
    const float* __restrict__ bias, float* __restrict__ Cout,
    int M, int N, int K)
{
    __shared__ float As[8][132];
    __shared__ float Bs[8][132];

    const float* A = (MODE == 1) ? (const float*)g_y : Ain;

    const int tid  = threadIdx.x;
    const int bm   = blockIdx.y * 128;
    const int bn   = blockIdx.x * 128;
    const int lrow = tid >> 1;          // 0..127
    const int lk4  = (tid & 1) << 2;    // 0 or 4
    const float* Ag = A  + (size_t)(bm + lrow) * K + lk4;
    const float* Bg = Bm + (size_t)(bn + lrow) * K + lk4;

    const int tx = tid & 15, ty = tid >> 4;
    const int c0 = tx * 8, r0 = ty * 8;

    float acc[8][8];
    #pragma unroll
    for (int i = 0; i < 8; i++)
        #pragma unroll
        for (int j = 0; j < 8; j++) acc[i][j] = 0.f;

    for (int k0 = 0; k0 < K; k0 += 8) {
        float4 a4 = *(const float4*)(Ag + k0);
        float4 b4 = *(const float4*)(Bg + k0);
        As[lk4 + 0][lrow] = a4.x; As[lk4 + 1][lrow] = a4.y;
        As[lk4 + 2][lrow] = a4.z; As[lk4 + 3][lrow] = a4.w;
        Bs[lk4 + 0][lrow] = b4.x; Bs[lk4 + 1][lrow] = b4.y;
        Bs[lk4 + 2][lrow] = b4.z; Bs[lk4 + 3][lrow] = b4.w;
        __syncthreads();
        #pragma unroll
        for (int kk = 0; kk < 8; kk++) {
            float ar[8], br[8];
            *(float4*)&ar[0] = *(const float4*)&As[kk][r0];
            *(float4*)&ar[4] = *(const float4*)&As[kk][r0 + 4];
            *(float4*)&br[0] = *(const float4*)&Bs[kk][c0];
            *(float4*)&br[4] = *(const float4*)&Bs[kk][c0 + 4];
            #pragma unroll
            for (int i = 0; i < 8; i++)
                #pragma unroll
                for (int j = 0; j < 8; j++)
                    acc[i][j] = fmaf(ar[i], br[j], acc[i][j]);
        }
        __syncthreads();
    }

    if (MODE == 0) {
        // n in [0,2304): comp = n/768 selects q/k/v; 768 % 128 == 0 so the
        // whole block lives in one component.
        const int comp = bn / C_;
        float* dstb = (comp == 0) ? g_q : (comp == 1) ? g_k : g_v;
        const int cbase = bn - comp * C_;
        #pragma unroll
        for (int i = 0; i < 8; i++) {
            const int m = bm + r0 + i;
            const int b = m >> 10, s = m & 1023;
            #pragma unroll
            for (int j = 0; j < 8; j++) {
                const int n = bn + c0 + j;
                const int c = cbase + c0 + j;
                const int h = c >> 6, d = c & 63;
                dstb[(size_t)(b * H_ + h) * (S_ * D_) + s * D_ + d] =
                    acc[i][j] + bias[n];
            }
        }
    } else {
        #pragma unroll
        for (int i = 0; i < 8; i++) {
            const int m = bm + r0 + i;
            #pragma unroll
            for (int j = 0; j < 8; j++) {
                const int n = bn + c0 + j;
                Cout[(size_t)m * N + n] = acc[i][j] + bias[n];
            }
        }
    }
}

// ---------------------------------------------------------------------------
// Flash attention, fp32, causal + key mask.
// grid: (S/64, B*H). 256 threads. Each CTA: 64 query rows of one (b,h).
// smem: sQ[d][r], sK[d][c] (transposed, pad 68), sP[r][t] (pad 68), sV[t][d].
// ---------------------------------------------------------------------------
#define ATTN_SMEM ((3 * 64 * 68 + 64 * 64) * 4)

__global__ __launch_bounds__(256) void attn_kernel(const int* __restrict__ mask)
{
    extern __shared__ float sm[];
    float (*sQ)[68] = (float(*)[68])(sm);
    float (*sK)[68] = (float(*)[68])(sm + 64 * 68);
    float (*sP)[68] = (float(*)[68])(sm + 2 * 64 * 68);
    float (*sV)[64] = (float(*)[64])(sm + 3 * 64 * 68);

    const int tid = threadIdx.x;
    const int bh  = blockIdx.y;
    const int b   = bh / H_;
    const int h   = bh - b * H_;
    const int it  = blockIdx.x;
    const int row0 = it * 64;

    const float* Q  = g_q + (size_t)bh * (S_ * D_) + (size_t)row0 * D_;
    const float* K0 = g_k + (size_t)bh * (S_ * D_);
    const float* V0 = g_v + (size_t)bh * (S_ * D_);
    const int* maskp = mask + b * S_;

    const int tx = tid & 15, ty = tid >> 4;
    const int tx4 = tx * 4, ty4 = ty * 4;

    // Load Q tile transposed: sQ[d][r]
    for (int i = tid; i < 64 * 16; i += 256) {
        const int r = i >> 4, d4 = (i & 15) << 2;
        float4 v = *(const float4*)(Q + r * D_ + d4);
        sQ[d4 + 0][r] = v.x; sQ[d4 + 1][r] = v.y;
        sQ[d4 + 2][r] = v.z; sQ[d4 + 3][r] = v.w;
    }

    int rg[4];
    #pragma unroll
    for (int i = 0; i < 4; i++) rg[i] = row0 + ty4 + i;

    float m_i[4], l_i[4], o[4][4];
    #pragma unroll
    for (int i = 0; i < 4; i++) {
        m_i[i] = -1e30f; l_i[i] = 0.f;
        #pragma unroll
        for (int j = 0; j < 4; j++) o[i][j] = 0.f;
    }

    for (int jt = 0; jt <= it; jt++) {
        __syncthreads();   // prev P@V reads done (first iter: Q load visible... see next sync)
        // Load K tile transposed + V tile direct
        const float* Kt = K0 + (size_t)jt * 64 * D_;
        const float* Vt = V0 + (size_t)jt * 64 * D_;
        for (int i = tid; i < 64 * 16; i += 256) {
            const int r = i >> 4, d4 = (i & 15) << 2;
            float4 kv = *(const float4*)(Kt + r * D_ + d4);
            sK[d4 + 0][r] = kv.x; sK[d4 + 1][r] = kv.y;
            sK[d4 + 2][r] = kv.z; sK[d4 + 3][r] = kv.w;
            *(float4*)&sV[r][d4] = *(const float4*)(Vt + r * D_ + d4);
        }
        __syncthreads();

        // Scores: s[i][j] = Q[rg[i]] . K[cbase+j]
        float s[4][4];
        #pragma unroll
        for (int i = 0; i < 4; i++)
            #pragma unroll
            for (int j = 0; j < 4; j++) s[i][j] = 0.f;

        #pragma unroll 8
        for (int d = 0; d < 64; d++) {
            float aq[4], bk[4];
            *(float4*)aq = *(const float4*)&sQ[d][ty4];
            *(float4*)bk = *(const float4*)&sK[d][tx4];
            #pragma unroll
            for (int i = 0; i < 4; i++)
                #pragma unroll
                for (int j = 0; j < 4; j++)
                    s[i][j] = fmaf(aq[i], bk[j], s[i][j]);
        }

        const int cbase = jt * 64 + tx4;
        int mk[4];
        #pragma unroll
        for (int j = 0; j < 4; j++) mk[j] = maskp[cbase + j];

        // Online softmax per row
        #pragma unroll
        for (int i = 0; i < 4; i++) {
            float sv[4];
            #pragma unroll
            for (int j = 0; j < 4; j++) {
                const bool ok = ((cbase + j) <= rg[i]) && (mk[j] != 0);
                sv[j] = ok ? s[i][j] * 0.125f : -1e30f;
            }
            float tm = fmaxf(fmaxf(sv[0], sv[1]), fmaxf(sv[2], sv[3]));
            #pragma unroll
            for (int off = 8; off >= 1; off >>= 1)
                tm = fmaxf(tm, __shfl_xor_sync(0xffffffffu, tm, off, 16));
            const float mnew = fmaxf(m_i[i], tm);
            const float f = __expf(m_i[i] - mnew);
            float pj[4], rs = 0.f;
            #pragma unroll
            for (int j = 0; j < 4; j++) {
                pj[j] = (sv[j] < -5e29f) ? 0.f : __expf(sv[j] - mnew);
                rs += pj[j];
            }
            #pragma unroll
            for (int off = 8; off >= 1; off >>= 1)
                rs += __shfl_xor_sync(0xffffffffu, rs, off, 16);
            l_i[i] = l_i[i] * f + rs;
            m_i[i] = mnew;
            #pragma unroll
            for (int j = 0; j < 4; j++) o[i][j] *= f;
            *(float4*)&sP[ty4 + i][tx4] = make_float4(pj[0], pj[1], pj[2], pj[3]);
        }
        __syncthreads();

        // O += P @ V
        #pragma unroll 8
        for (int t = 0; t < 64; t++) {
            float vv[4];
            *(float4*)vv = *(const float4*)&sV[t][tx4];
            float ap[4];
            #pragma unroll
            for (int i = 0; i < 4; i++) ap[i] = sP[ty4 + i][t];
            #pragma unroll
            for (int i = 0; i < 4; i++)
                #pragma unroll
                for (int j = 0; j < 4; j++)
                    o[i][j] = fmaf(ap[i], vv[j], o[i][j]);
        }
    }

    // Write y[B,S,C]
    #pragma unroll
    for (int i = 0; i < 4; i++) {
        const float inv = (l_i[i] > 0.f) ? (1.f / l_i[i]) : 0.f;
        float4 r4 = make_float4(o[i][0] * inv, o[i][1] * inv,
                                o[i][2] * inv, o[i][3] * inv);
        *(float4*)&g_y[(size_t)(b * S_ + rg[i]) * C_ + h * D_ + tx4] = r4;
    }
}

// ---------------------------------------------------------------------------
extern "C" void kernel_launch(void* const* d_in, const int* in_sizes, int n_in,
                              void* d_out, int out_size)
{
    const float* x      = (const float*)d_in[0];
    const float* w_qkv  = (const float*)d_in[1];
    const float* b_qkv  = (const float*)d_in[2];
    const float* w_out  = (const float*)d_in[3];
    const float* b_out  = (const float*)d_in[4];
    const int*   amask  = (const int*)d_in[5];
    float* out = (float*)d_out;

    cudaFuncSetAttribute(attn_kernel,
                         cudaFuncAttributeMaxDynamicSharedMemorySize, ATTN_SMEM);

    // 1) QKV projection -> g_q/g_k/g_v [B,H,S,D]
    {
        dim3 grid((3 * C_) / 128, BS_ / 128);   // (18, 64)
        sgemm_nt<0><<<grid, 256>>>(x, w_qkv, b_qkv, nullptr, BS_, 3 * C_, C_);
    }
    // 2) Causal flash attention -> g_y [B,S,C]
    {
        dim3 grid(S_ / 64, B_ * H_);            // (16, 96)
        attn_kernel<<<grid, 256, ATTN_SMEM>>>(amask);
    }
    // 3) Output projection -> d_out
    {
        dim3 grid(C_ / 128, BS_ / 128);         // (6, 64)
        sgemm_nt<1><<<grid, 256>>>(nullptr, w_out, b_out, out, BS_, C_, C_);
    }
}

// round 5
// speedup vs baseline: 1.6624x; 1.6624x over previous
#include <cuda_runtime.h>
#include <cstdint>

// Problem constants
#define B_  8
#define S_  1024
#define C_  768
#define H_  12
#define D_  64
#define BS_ (B_ * S_)            // 8192
#define BHSD (B_ * H_ * S_ * D_) // 6291456

// Scratch (allocation-free: static device globals)
__device__ float g_q[BHSD];
__device__ float g_k[BHSD];
__device__ float g_v[BHSD];
__device__ float g_y[BS_ * C_];

// ---------------------------------------------------------------------------
// mma.sync tf32 helpers (base sm_103 ISA — no tcgen05)
// ---------------------------------------------------------------------------
__device__ __forceinline__ uint32_t f2tf32(float f) {
    uint32_t r;
    asm("cvt.rna.tf32.f32 %0, %1;" : "=r"(r) : "f"(f));
    return r;
}

__device__ __forceinline__ void mma_tf32(float* c, const uint32_t* a,
                                         const uint32_t* b) {
    asm volatile(
        "mma.sync.aligned.m16n8k8.row.col.f32.tf32.tf32.f32 "
        "{%0,%1,%2,%3}, {%4,%5,%6,%7}, {%8,%9}, {%0,%1,%2,%3};"
        : "+f"(c[0]), "+f"(c[1]), "+f"(c[2]), "+f"(c[3])
        : "r"(a[0]), "r"(a[1]), "r"(a[2]), "r"(a[3]), "r"(b[0]), "r"(b[1]));
}

// ===========================================================================
// Tensor-core GEMM NT: C[m,n] = sum_k A[m,k]*B[n,k] + bias[n]
// 128x128 CTA tile, BK=32, 8 warps (2x4), warp tile 64x32.
// mma.sync m16n8k8 tf32. MODE 0: A = x, scatter to g_q/g_k/g_v ([B,H,S,D]);
// MODE 1: A = g_y -> Cout ([M,C]).
// ===========================================================================
template <int MODE>
__global__ __launch_bounds__(256) void mmagemm(
    const float* __restrict__ Ain, const float* __restrict__ Bm,
    const float* __restrict__ bias, float* __restrict__ Cout)
{
    __shared__ uint32_t As[128][36];
    __shared__ uint32_t Bs[128][36];

    const float* A = (MODE == 1) ? (const float*)g_y : Ain;

    const int tid  = threadIdx.x;
    const int wid  = tid >> 5;
    const int lane = tid & 31;
    const int g = lane >> 2;        // 0..7
    const int t = lane & 3;         // 0..3
    const int wr = (wid >> 2) * 64; // warp row base within tile
    const int wc = (wid & 3) * 32;  // warp col base within tile
    const int bm = blockIdx.y * 128;
    const int bn = blockIdx.x * 128;

    float acc[4][4][4];             // [mtile][ntile][frag]
    #pragma unroll
    for (int i = 0; i < 4; i++)
        #pragma unroll
        for (int j = 0; j < 4; j++)
            #pragma unroll
            for (int r = 0; r < 4; r++) acc[i][j][r] = 0.f;

    for (int k0 = 0; k0 < C_; k0 += 32) {
        // Stage A/B chunks (128 rows x 32 fp32), converting fp32 -> tf32 (rna)
        #pragma unroll
        for (int i = 0; i < 4; i++) {
            const int idx = tid + i * 256;      // 0..1023
            const int row = idx >> 3;           // 0..127
            const int f4  = (idx & 7) << 2;     // 0,4,..,28
            float4 va = *(const float4*)(A  + (size_t)(bm + row) * C_ + k0 + f4);
            float4 vb = *(const float4*)(Bm + (size_t)(bn + row) * C_ + k0 + f4);
            uint4 ua = make_uint4(f2tf32(va.x), f2tf32(va.y),
                                  f2tf32(va.z), f2tf32(va.w));
            uint4 ub = make_uint4(f2tf32(vb.x), f2tf32(vb.y),
                                  f2tf32(vb.z), f2tf32(vb.w));
            *(uint4*)&As[row][f4] = ua;
            *(uint4*)&Bs[row][f4] = ub;
        }
        __syncthreads();

        #pragma unroll
        for (int ks = 0; ks < 4; ks++) {
            const int kc = ks * 8;
            uint32_t af[4][4], bf[4][2];
            #pragma unroll
            for (int mt = 0; mt < 4; mt++) {
                const int r = wr + mt * 16 + g;
                af[mt][0] = As[r][kc + t];
                af[mt][1] = As[r + 8][kc + t];
                af[mt][2] = As[r][kc + t + 4];
                af[mt][3] = As[r + 8][kc + t + 4];
            }
            #pragma unroll
            for (int nt = 0; nt < 4; nt++) {
                const int n = wc + nt * 8 + g;
                bf[nt][0] = Bs[n][kc + t];
                bf[nt][1] = Bs[n][kc + t + 4];
            }
            #pragma unroll
            for (int mt = 0; mt < 4; mt++)
                #pragma unroll
                for (int nt = 0; nt < 4; nt++)
                    mma_tf32(acc[mt][nt], af[mt], bf[nt]);
        }
        __syncthreads();
    }

    // Epilogue: c0,c1 -> row g, cols 2t,2t+1 ; c2,c3 -> row g+8
    #pragma unroll
    for (int mt = 0; mt < 4; mt++) {
        #pragma unroll
        for (int nt = 0; nt < 4; nt++) {
            const int col = wc + nt * 8 + 2 * t;     // within 128 tile (even)
            const int r0  = bm + wr + mt * 16 + g;
            const int r1  = r0 + 8;
            const float bv0 = bias[bn + col];
            const float bv1 = bias[bn + col + 1];
            float2 lo = make_float2(acc[mt][nt][0] + bv0, acc[mt][nt][1] + bv1);
            float2 hi = make_float2(acc[mt][nt][2] + bv0, acc[mt][nt][3] + bv1);
            if (MODE == 0) {
                const int comp = bn / C_;            // 768 % 128 == 0
                float* db = (comp == 0) ? g_q : (comp == 1) ? g_k : g_v;
                const int c = bn - comp * C_ + col;
                const int h = c >> 6, d = c & 63;
                {
                    const int b = r0 >> 10, s = r0 & 1023;
                    *(float2*)(db + (size_t)(b * H_ + h) * (S_ * D_) +
                               (size_t)s * D_ + d) = lo;
                }
                {
                    const int b = r1 >> 10, s = r1 & 1023;
                    *(float2*)(db + (size_t)(b * H_ + h) * (S_ * D_) +
                               (size_t)s * D_ + d) = hi;
                }
            } else {
                *(float2*)(Cout + (size_t)r0 * C_ + bn + col) = lo;
                *(float2*)(Cout + (size_t)r1 * C_ + bn + col) = hi;
            }
        }
    }
}

// ---------------------------------------------------------------------------
// Flash attention, fp32, causal + key mask (unchanged from R2 — correct).
// ---------------------------------------------------------------------------
#define ATTN_SMEM ((3 * 64 * 68 + 64 * 64) * 4)

__global__ __launch_bounds__(256) void attn_kernel(const int* __restrict__ mask)
{
    extern __shared__ float sm[];
    float (*sQ)[68] = (float(*)[68])(sm);
    float (*sK)[68] = (float(*)[68])(sm + 64 * 68);
    float (*sP)[68] = (float(*)[68])(sm + 2 * 64 * 68);
    float (*sV)[64] = (float(*)[64])(sm + 3 * 64 * 68);

    const int tid = threadIdx.x;
    const int bh  = blockIdx.y;
    const int b   = bh / H_;
    const int h   = bh - b * H_;
    const int it  = blockIdx.x;
    const int row0 = it * 64;

    const float* Q  = g_q + (size_t)bh * (S_ * D_) + (size_t)row0 * D_;
    const float* K0 = g_k + (size_t)bh * (S_ * D_);
    const float* V0 = g_v + (size_t)bh * (S_ * D_);
    const int* maskp = mask + b * S_;

    const int tx = tid & 15, ty = tid >> 4;
    const int tx4 = tx * 4, ty4 = ty * 4;

    for (int i = tid; i < 64 * 16; i += 256) {
        const int r = i >> 4, d4 = (i & 15) << 2;
        float4 v = *(const float4*)(Q + r * D_ + d4);
        sQ[d4 + 0][r] = v.x; sQ[d4 + 1][r] = v.y;
        sQ[d4 + 2][r] = v.z; sQ[d4 + 3][r] = v.w;
    }

    int rg[4];
    #pragma unroll
    for (int i = 0; i < 4; i++) rg[i] = row0 + ty4 + i;

    float m_i[4], l_i[4], o[4][4];
    #pragma unroll
    for (int i = 0; i < 4; i++) {
        m_i[i] = -1e30f; l_i[i] = 0.f;
        #pragma unroll
        for (int j = 0; j < 4; j++) o[i][j] = 0.f;
    }

    for (int jt = 0; jt <= it; jt++) {
        __syncthreads();
        const float* Kt = K0 + (size_t)jt * 64 * D_;
        const float* Vt = V0 + (size_t)jt * 64 * D_;
        for (int i = tid; i < 64 * 16; i += 256) {
            const int r = i >> 4, d4 = (i & 15) << 2;
            float4 kv = *(const float4*)(Kt + r * D_ + d4);
            sK[d4 + 0][r] = kv.x; sK[d4 + 1][r] = kv.y;
            sK[d4 + 2][r] = kv.z; sK[d4 + 3][r] = kv.w;
            *(float4*)&sV[r][d4] = *(const float4*)(Vt + r * D_ + d4);
        }
        __syncthreads();

        float s[4][4];
        #pragma unroll
        for (int i = 0; i < 4; i++)
            #pragma unroll
            for (int j = 0; j < 4; j++) s[i][j] = 0.f;

        #pragma unroll 8
        for (int d = 0; d < 64; d++) {
            float aq[4], bk[4];
            *(float4*)aq = *(const float4*)&sQ[d][ty4];
            *(float4*)bk = *(const float4*)&sK[d][tx4];
            #pragma unroll
            for (int i = 0; i < 4; i++)
                #pragma unroll
                for (int j = 0; j < 4; j++)
                    s[i][j] = fmaf(aq[i], bk[j], s[i][j]);
        }

        const int cbase = jt * 64 + tx4;
        int mk[4];
        #pragma unroll
        for (int j = 0; j < 4; j++) mk[j] = maskp[cbase + j];

        #pragma unroll
        for (int i = 0; i < 4; i++) {
            float sv[4];
            #pragma unroll
            for (int j = 0; j < 4; j++) {
                const bool ok = ((cbase + j) <= rg[i]) && (mk[j] != 0);
                sv[j] = ok ? s[i][j] * 0.125f : -1e30f;
            }
            float tm = fmaxf(fmaxf(sv[0], sv[1]), fmaxf(sv[2], sv[3]));
            #pragma unroll
            for (int off = 8; off >= 1; off >>= 1)
                tm = fmaxf(tm, __shfl_xor_sync(0xffffffffu, tm, off, 16));
            const float mnew = fmaxf(m_i[i], tm);
            const float f = __expf(m_i[i] - mnew);
            float pj[4], rs = 0.f;
            #pragma unroll
            for (int j = 0; j < 4; j++) {
                pj[j] = (sv[j] < -5e29f) ? 0.f : __expf(sv[j] - mnew);
                rs += pj[j];
            }
            #pragma unroll
            for (int off = 8; off >= 1; off >>= 1)
                rs += __shfl_xor_sync(0xffffffffu, rs, off, 16);
            l_i[i] = l_i[i] * f + rs;
            m_i[i] = mnew;
            #pragma unroll
            for (int j = 0; j < 4; j++) o[i][j] *= f;
            *(float4*)&sP[ty4 + i][tx4] = make_float4(pj[0], pj[1], pj[2], pj[3]);
        }
        __syncthreads();

        #pragma unroll 8
        for (int tcol = 0; tcol < 64; tcol++) {
            float vv[4];
            *(float4*)vv = *(const float4*)&sV[tcol][tx4];
            float ap[4];
            #pragma unroll
            for (int i = 0; i < 4; i++) ap[i] = sP[ty4 + i][tcol];
            #pragma unroll
            for (int i = 0; i < 4; i++)
                #pragma unroll
                for (int j = 0; j < 4; j++)
                    o[i][j] = fmaf(ap[i], vv[j], o[i][j]);
        }
    }

    #pragma unroll
    for (int i = 0; i < 4; i++) {
        const float inv = (l_i[i] > 0.f) ? (1.f / l_i[i]) : 0.f;
        float4 r4 = make_float4(o[i][0] * inv, o[i][1] * inv,
                                o[i][2] * inv, o[i][3] * inv);
        *(float4*)&g_y[(size_t)(b * S_ + rg[i]) * C_ + h * D_ + tx4] = r4;
    }
}

// ---------------------------------------------------------------------------
extern "C" void kernel_launch(void* const* d_in, const int* in_sizes, int n_in,
                              void* d_out, int out_size)
{
    const float* x      = (const float*)d_in[0];
    const float* w_qkv  = (const float*)d_in[1];
    const float* b_qkv  = (const float*)d_in[2];
    const float* w_out  = (const float*)d_in[3];
    const float* b_out  = (const float*)d_in[4];
    const int*   amask  = (const int*)d_in[5];
    float* out = (float*)d_out;

    cudaFuncSetAttribute(attn_kernel,
                         cudaFuncAttributeMaxDynamicSharedMemorySize, ATTN_SMEM);

    // 1) QKV projection (mma.sync tf32) -> g_q/g_k/g_v [B,H,S,D]
    {
        dim3 grid((3 * C_) / 128, BS_ / 128);   // (18, 64)
        mmagemm<0><<<grid, 256>>>(x, w_qkv, b_qkv, nullptr);
    }
    // 2) Causal flash attention -> g_y [B,S,C]
    {
        dim3 grid(S_ / 64, B_ * H_);            // (16, 96)
        attn_kernel<<<grid, 256, ATTN_SMEM>>>(amask);
    }
    // 3) Output projection (mma.sync tf32) -> d_out
    {
        dim3 grid(C_ / 128, BS_ / 128);         // (6, 64)
        mmagemm<1><<<grid, 256>>>(nullptr, w_out, b_out, out);
    }
}

// round 9
// speedup vs baseline: 2.3889x; 1.4370x over previous
#include <cuda_runtime.h>
#include <cstdint>

// Problem constants
#define B_  8
#define S_  1024
#define C_  768
#define H_  12
#define D_  64
#define BS_ (B_ * S_)            // 8192
#define BHSD (B_ * H_ * S_ * D_) // 6291456

// Scratch (allocation-free: static device globals)
__device__ float g_q[BHSD];
__device__ float g_k[BHSD];
__device__ float g_v[BHSD];
__device__ float g_y[BS_ * C_];

// ---------------------------------------------------------------------------
// mma.sync tf32 helpers (base sm_103 ISA)
// ---------------------------------------------------------------------------
__device__ __forceinline__ uint32_t f2tf32(float f) {
    uint32_t r;
    asm("cvt.rna.tf32.f32 %0, %1;" : "=r"(r) : "f"(f));
    return r;
}
__device__ __forceinline__ float fexp2(float x) {
    float y;
    asm("ex2.approx.f32 %0, %1;" : "=f"(y) : "f"(x));
    return y;
}
__device__ __forceinline__ void mma_tf32(float* c, const uint32_t* a,
                                         const uint32_t* b) {
    asm volatile(
        "mma.sync.aligned.m16n8k8.row.col.f32.tf32.tf32.f32 "
        "{%0,%1,%2,%3}, {%4,%5,%6,%7}, {%8,%9}, {%0,%1,%2,%3};"
        : "+f"(c[0]), "+f"(c[1]), "+f"(c[2]), "+f"(c[3])
        : "r"(a[0]), "r"(a[1]), "r"(a[2]), "r"(a[3]), "r"(b[0]), "r"(b[1]));
}

// ===========================================================================
// Tensor-core GEMM NT (unchanged from R4 — known correct)
// ===========================================================================
template <int MODE>
__global__ __launch_bounds__(256) void mmagemm(
    const float* __restrict__ Ain, const float* __restrict__ Bm,
    const float* __restrict__ bias, float* __restrict__ Cout)
{
    __shared__ uint32_t As[128][36];
    __shared__ uint32_t Bs[128][36];

    const float* A = (MODE == 1) ? (const float*)g_y : Ain;

    const int tid  = threadIdx.x;
    const int wid  = tid >> 5;
    const int lane = tid & 31;
    const int g = lane >> 2;
    const int t = lane & 3;
    const int wr = (wid >> 2) * 64;
    const int wc = (wid & 3) * 32;
    const int bm = blockIdx.y * 128;
    const int bn = blockIdx.x * 128;

    float acc[4][4][4];
    #pragma unroll
    for (int i = 0; i < 4; i++)
        #pragma unroll
        for (int j = 0; j < 4; j++)
            #pragma unroll
            for (int r = 0; r < 4; r++) acc[i][j][r] = 0.f;

    for (int k0 = 0; k0 < C_; k0 += 32) {
        #pragma unroll
        for (int i = 0; i < 4; i++) {
            const int idx = tid + i * 256;
            const int row = idx >> 3;
            const int f4  = (idx & 7) << 2;
            float4 va = *(const float4*)(A  + (size_t)(bm + row) * C_ + k0 + f4);
            float4 vb = *(const float4*)(Bm + (size_t)(bn + row) * C_ + k0 + f4);
            uint4 ua = make_uint4(f2tf32(va.x), f2tf32(va.y),
                                  f2tf32(va.z), f2tf32(va.w));
            uint4 ub = make_uint4(f2tf32(vb.x), f2tf32(vb.y),
                                  f2tf32(vb.z), f2tf32(vb.w));
            *(uint4*)&As[row][f4] = ua;
            *(uint4*)&Bs[row][f4] = ub;
        }
        __syncthreads();

        #pragma unroll
        for (int ks = 0; ks < 4; ks++) {
            const int kc = ks * 8;
            uint32_t af[4][4], bf[4][2];
            #pragma unroll
            for (int mt = 0; mt < 4; mt++) {
                const int r = wr + mt * 16 + g;
                af[mt][0] = As[r][kc + t];
                af[mt][1] = As[r + 8][kc + t];
                af[mt][2] = As[r][kc + t + 4];
                af[mt][3] = As[r + 8][kc + t + 4];
            }
            #pragma unroll
            for (int nt = 0; nt < 4; nt++) {
                const int n = wc + nt * 8 + g;
                bf[nt][0] = Bs[n][kc + t];
                bf[nt][1] = Bs[n][kc + t + 4];
            }
            #pragma unroll
            for (int mt = 0; mt < 4; mt++)
                #pragma unroll
                for (int nt = 0; nt < 4; nt++)
                    mma_tf32(acc[mt][nt], af[mt], bf[nt]);
        }
        __syncthreads();
    }

    #pragma unroll
    for (int mt = 0; mt < 4; mt++) {
        #pragma unroll
        for (int nt = 0; nt < 4; nt++) {
            const int col = wc + nt * 8 + 2 * t;
            const int r0  = bm + wr + mt * 16 + g;
            const int r1  = r0 + 8;
            const float bv0 = bias[bn + col];
            const float bv1 = bias[bn + col + 1];
            float2 lo = make_float2(acc[mt][nt][0] + bv0, acc[mt][nt][1] + bv1);
            float2 hi = make_float2(acc[mt][nt][2] + bv0, acc[mt][nt][3] + bv1);
            if (MODE == 0) {
                const int comp = bn / C_;
                float* db = (comp == 0) ? g_q : (comp == 1) ? g_k : g_v;
                const int c = bn - comp * C_ + col;
                const int h = c >> 6, d = c & 63;
                {
                    const int b = r0 >> 10, s = r0 & 1023;
                    *(float2*)(db + (size_t)(b * H_ + h) * (S_ * D_) +
                               (size_t)s * D_ + d) = lo;
                }
                {
                    const int b = r1 >> 10, s = r1 & 1023;
                    *(float2*)(db + (size_t)(b * H_ + h) * (S_ * D_) +
                               (size_t)s * D_ + d) = hi;
                }
            } else {
                *(float2*)(Cout + (size_t)r0 * C_ + bn + col) = lo;
                *(float2*)(Cout + (size_t)r1 * C_ + bn + col) = hi;
            }
        }
    }
}

// ===========================================================================
// Flash attention, both matmuls on mma.sync tf32.
// FIXED vs R5-R7: smem row strides now hold the full 64-dim tiles
//   sQ[128][68], sK[32][68] (tf32), sV[32][72] (tf32), sSP[128][36] (fp32).
// QK^T mma -> S spill (validated C-layout) -> in-place SIMT softmax ->
// P@V mma (P read as float, bit-cast per register; no memory type-punning).
// grid: (8, 96), 256 threads, 8 warps x 16 query rows. Key tiles of 32.
// Base-2 softmax; 0.125*log2(e) folded into Q staging.
// ===========================================================================
#define AT_SQ   0
#define AT_SK   (128 * 68)                      // 8704
#define AT_SV   (AT_SK + 32 * 68)               // 10880
#define AT_SS   (AT_SV + 32 * 72)               // 13184
#define AT_SFAC (AT_SS + 128 * 36)              // 17792
#define AT_SL   (AT_SFAC + 128)                 // 17920
#define AT_SMEM_WORDS (AT_SL + 128)             // 18048
#define AT_SMEM_BYTES (AT_SMEM_WORDS * 4)       // 72192
#define QSCALE 0.18033688011f                   // 0.125 * log2(e)

__global__ __launch_bounds__(256) void attn_mma(const int* __restrict__ mask)
{
    extern __shared__ uint32_t su[];
    uint32_t (*sQ)[68]  = (uint32_t(*)[68])(su + AT_SQ);
    uint32_t (*sK)[68]  = (uint32_t(*)[68])(su + AT_SK);
    uint32_t (*sV)[72]  = (uint32_t(*)[72])(su + AT_SV);
    float    (*sSP)[36] = (float(*)[36])(su + AT_SS);
    float* sFac = (float*)(su + AT_SFAC);
    float* sL   = (float*)(su + AT_SL);

    const int tid  = threadIdx.x;
    const int wid  = tid >> 5;
    const int lane = tid & 31;
    const int g = lane >> 2;
    const int t = lane & 3;
    const int m0 = wid * 16;

    const int it  = (int)gridDim.x - 1 - (int)blockIdx.x;  // heavy tiles first
    const int bh  = blockIdx.y;
    const int b   = bh / H_;
    const int h   = bh - b * H_;
    const int row0 = it * 128;

    const float* Q  = g_q + (size_t)bh * (S_ * D_) + (size_t)row0 * D_;
    const float* K0 = g_k + (size_t)bh * (S_ * D_);
    const float* V0 = g_v + (size_t)bh * (S_ * D_);
    const int* maskp = mask + b * S_;

    // Stage Q (tf32, scale folded): 128 rows x 64 dims
    #pragma unroll
    for (int i = 0; i < 8; i++) {
        const int idx = tid + i * 256;          // 0..2047
        const int r = idx >> 4, c4 = (idx & 15) << 2;
        float4 v = *(const float4*)(Q + r * D_ + c4);
        sQ[r][c4 + 0] = f2tf32(v.x * QSCALE);
        sQ[r][c4 + 1] = f2tf32(v.y * QSCALE);
        sQ[r][c4 + 2] = f2tf32(v.z * QSCALE);
        sQ[r][c4 + 3] = f2tf32(v.w * QSCALE);
    }

    // Softmax ownership: thread tid owns row tid>>1, cols (tid&1)*16..+15
    const int srow  = tid >> 1;
    const int scol0 = (tid & 1) << 4;
    const int growo = row0 + srow;
    float m_row = -1e30f, l_row = 0.f;

    // Fragment O accumulators: warp rows m0+g / m0+g+8, 8 n-tiles of 8 dims
    float o[8][4];
    #pragma unroll
    for (int nv = 0; nv < 8; nv++)
        #pragma unroll
        for (int r = 0; r < 4; r++) o[nv][r] = 0.f;

    const int ntiles = 4 * it + 4;
    for (int jt = 0; jt < ntiles; jt++) {
        const int kb = jt * 32;
        __syncthreads();    // prev P@V done reading sSP/sV
        // Stage K and V tiles (32 rows x 64 dims each), tf32
        #pragma unroll
        for (int i = 0; i < 2; i++) {
            const int idx = tid + i * 256;      // 0..511
            const int r = idx >> 4, c4 = (idx & 15) << 2;
            float4 kv = *(const float4*)(K0 + (size_t)(kb + r) * D_ + c4);
            float4 vv = *(const float4*)(V0 + (size_t)(kb + r) * D_ + c4);
            sK[r][c4 + 0] = f2tf32(kv.x);
            sK[r][c4 + 1] = f2tf32(kv.y);
            sK[r][c4 + 2] = f2tf32(kv.z);
            sK[r][c4 + 3] = f2tf32(kv.w);
            sV[r][c4 + 0] = f2tf32(vv.x);
            sV[r][c4 + 1] = f2tf32(vv.y);
            sV[r][c4 + 2] = f2tf32(vv.z);
            sV[r][c4 + 3] = f2tf32(vv.w);
        }
        __syncthreads();

        // S = Q K^T : warp tile 16x32 (nt=4), 8 k-steps [validated pattern]
        float sacc[4][4];
        #pragma unroll
        for (int nt = 0; nt < 4; nt++)
            #pragma unroll
            for (int r = 0; r < 4; r++) sacc[nt][r] = 0.f;

        #pragma unroll
        for (int ks = 0; ks < 8; ks++) {
            const int kc = ks * 8;
            uint32_t af[4];
            af[0] = sQ[m0 + g][kc + t];
            af[1] = sQ[m0 + g + 8][kc + t];
            af[2] = sQ[m0 + g][kc + t + 4];
            af[3] = sQ[m0 + g + 8][kc + t + 4];
            #pragma unroll
            for (int nt = 0; nt < 4; nt++) {
                uint32_t bf[2];
                bf[0] = sK[nt * 8 + g][kc + t];
                bf[1] = sK[nt * 8 + g][kc + t + 4];
                mma_tf32(sacc[nt], af, bf);
            }
        }

        // Spill S fragments to sSP (validated C-layout), plain float
        #pragma unroll
        for (int nt = 0; nt < 4; nt++) {
            const int col = nt * 8 + 2 * t;
            *(float2*)&sSP[m0 + g][col] =
                make_float2(sacc[nt][0], sacc[nt][1]);
            *(float2*)&sSP[m0 + g + 8][col] =
                make_float2(sacc[nt][2], sacc[nt][3]);
        }
        __syncthreads();

        // SIMT softmax, in place (single float type)
        {
            float sv[16];
            int   km[16];
            #pragma unroll
            for (int j4 = 0; j4 < 4; j4++)
                *(int4*)&km[j4 * 4] =
                    *(const int4*)(maskp + kb + scol0 + j4 * 4);
            #pragma unroll
            for (int j = 0; j < 16; j++) {
                const int col = kb + scol0 + j;
                const bool ok = (col <= growo) && (km[j] != 0);
                sv[j] = ok ? sSP[srow][scol0 + j] : -1e30f;
            }
            float lm = sv[0];
            #pragma unroll
            for (int j = 1; j < 16; j++) lm = fmaxf(lm, sv[j]);
            lm = fmaxf(lm, __shfl_xor_sync(0xffffffffu, lm, 1));
            const float mnew = fmaxf(fmaxf(m_row, lm), -50.0f);
            const float fac = fexp2(m_row - mnew);
            float rs = 0.f;
            #pragma unroll
            for (int j = 0; j < 16; j++) {
                const float p = fexp2(sv[j] - mnew);
                rs += p;
                sSP[srow][scol0 + j] = p;
            }
            rs += __shfl_xor_sync(0xffffffffu, rs, 1);
            l_row = l_row * fac + rs;
            m_row = mnew;
            if ((tid & 1) == 0) sFac[srow] = fac;
        }
        __syncthreads();

        // Rescale O by this tile's per-row factors
        const float f0 = sFac[m0 + g];
        const float f1 = sFac[m0 + g + 8];
        #pragma unroll
        for (int nv = 0; nv < 8; nv++) {
            o[nv][0] *= f0; o[nv][1] *= f0;
            o[nv][2] *= f1; o[nv][3] *= f1;
        }

        // O += P @ V : A = P (16x32, float->tf32 bit-cast in register),
        //              B = sV (32x64 tf32), 4 k-steps x 8 d-tiles
        #pragma unroll
        for (int ks = 0; ks < 4; ks++) {
            const int kc = ks * 8;
            uint32_t af[4];
            af[0] = __float_as_uint(sSP[m0 + g][kc + t]);
            af[1] = __float_as_uint(sSP[m0 + g + 8][kc + t]);
            af[2] = __float_as_uint(sSP[m0 + g][kc + t + 4]);
            af[3] = __float_as_uint(sSP[m0 + g + 8][kc + t + 4]);
            #pragma unroll
            for (int nv = 0; nv < 8; nv++) {
                uint32_t bf[2];
                bf[0] = sV[kc + t][nv * 8 + g];
                bf[1] = sV[kc + t + 4][nv * 8 + g];
                mma_tf32(o[nv], af, bf);
            }
        }
    }

    // Publish per-row normalizers
    if ((tid & 1) == 0) sL[srow] = l_row;
    __syncthreads();

    // Epilogue: normalize and write y[B,S,C] (fragment C-layout)
    const int gr0 = row0 + m0 + g;
    const int gr1 = gr0 + 8;
    const float lv0 = sL[m0 + g];
    const float lv1 = sL[m0 + g + 8];
    const float inv0 = (lv0 > 0.f) ? (1.f / lv0) : 0.f;
    const float inv1 = (lv1 > 0.f) ? (1.f / lv1) : 0.f;
    float* y0 = g_y + (size_t)(b * S_ + gr0) * C_ + h * D_;
    float* y1 = g_y + (size_t)(b * S_ + gr1) * C_ + h * D_;
    #pragma unroll
    for (int nv = 0; nv < 8; nv++) {
        const int col = nv * 8 + 2 * t;
        *(float2*)(y0 + col) = make_float2(o[nv][0] * inv0, o[nv][1] * inv0);
        *(float2*)(y1 + col) = make_float2(o[nv][2] * inv1, o[nv][3] * inv1);
    }
}

// ---------------------------------------------------------------------------
extern "C" void kernel_launch(void* const* d_in, const int* in_sizes, int n_in,
                              void* d_out, int out_size)
{
    const float* x      = (const float*)d_in[0];
    const float* w_qkv  = (const float*)d_in[1];
    const float* b_qkv  = (const float*)d_in[2];
    const float* w_out  = (const float*)d_in[3];
    const float* b_out  = (const float*)d_in[4];
    const int*   amask  = (const int*)d_in[5];
    float* out = (float*)d_out;

    cudaFuncSetAttribute(attn_mma,
                         cudaFuncAttributeMaxDynamicSharedMemorySize,
                         AT_SMEM_BYTES);

    // 1) QKV projection (mma.sync tf32) -> g_q/g_k/g_v [B,H,S,D]
    {
        dim3 grid((3 * C_) / 128, BS_ / 128);   // (18, 64)
        mmagemm<0><<<grid, 256>>>(x, w_qkv, b_qkv, nullptr);
    }
    // 2) Flash attention (mma QK^T + SIMT softmax + mma PV) -> g_y
    {
        dim3 grid(S_ / 128, B_ * H_);           // (8, 96)
        attn_mma<<<grid, 256, AT_SMEM_BYTES>>>(amask);
    }
    // 3) Output projection (mma.sync tf32) -> d_out
    {
        dim3 grid(C_ / 128, BS_ / 128);         // (6, 64)
        mmagemm<1><<<grid, 256>>>(nullptr, w_out, b_out, out);
    }
}